// round 13
// baseline (speedup 1.0000x reference)
#include <cuda_runtime.h>
#include <cuda_fp16.h>
#include <cstdint>

// ============================================================================
// out[t] = 0.5*( softmaxN(G+Bn)V + vn + softmaxC(G+Bc; seg==c_t)V + vc )
// G = Q.K^T via mma.sync HMMA fp16. Unnormalized exp2 weights as PV A-frags;
// two fp32 accumulators; counter==2.
// R13: ring-3 K/V overlaid on dead Q smem -> ONE barrier per chunk; tok_kernel
// deleted (bmat blocks self-compute tokens, run first in fused prep grid).
// Numerics identical to R12.
// ============================================================================

#define SCL 0.18033688011112042f   // 0.125 * log2(e)

__device__ float g_tok[9 * 192];        // only v-part rows [128..192) used now
__device__ __half g_Rt[64 * 8 * 1024];  // [bh][c][s] masked exp2(SCL*(Bc-Bn)), fp16
__device__ float g_bn2[64 * 1024];      // [bh][s] = SCL*Bn
// preconverted fp16 tile images (swizzled smem byte-images, pitch-128 tiles)
__device__ __align__(16) unsigned char g_q16[64 * 16 * 8192];   // [bh][qtile 64t]
__device__ __align__(16) unsigned char g_k16[64 * 16 * 8192];   // [bh][ktile 64s]
__device__ __align__(16) unsigned char g_vh [64 * 16 * 8192];   // [bh][vtile 64s]

__device__ __forceinline__ uint32_t smem_u32(const void* p) {
    uint32_t a;
    asm("{ .reg .u64 t; cvta.to.shared.u64 t, %1; cvt.u32.u64 %0, t; }" : "=r"(a) : "l"(p));
    return a;
}
__device__ __forceinline__ float ex2f(float x) {
    float y; asm("ex2.approx.f32 %0, %1;" : "=f"(y) : "f"(x)); return y;
}
__device__ __forceinline__ uint32_t ex2h2(uint32_t x) {
    uint32_t r; asm("ex2.approx.f16x2 %0, %1;" : "=r"(r) : "r"(x)); return r;
}
__device__ __forceinline__ uint32_t packh2(float lo, float hi) {
    uint32_t r; asm("cvt.rn.f16x2.f32 %0, %1, %2;" : "=r"(r) : "f"(hi), "f"(lo)); return r;
}
__device__ __forceinline__ uint32_t mulh2(uint32_t a, uint32_t b) {
    uint32_t r; asm("mul.rn.f16x2 %0, %1, %2;" : "=r"(r) : "r"(a), "r"(b)); return r;
}
// pitch-128 swizzle for 64-wide fp16 tiles: row=ch, byte col = s*2
__device__ __forceinline__ uint32_t SW128(uint32_t row, uint32_t bcol) {
    return row * 128u + (bcol ^ ((row & 7u) << 4));
}
__device__ __forceinline__ void ldsm4t(uint32_t* r, uint32_t addr) {
    asm volatile("ldmatrix.sync.aligned.m8n8.x4.trans.shared.b16 {%0,%1,%2,%3}, [%4];"
        : "=r"(r[0]), "=r"(r[1]), "=r"(r[2]), "=r"(r[3]) : "r"(addr));
}
__device__ __forceinline__ void ldsm4(uint32_t* r, uint32_t addr) {
    asm volatile("ldmatrix.sync.aligned.m8n8.x4.shared.b16 {%0,%1,%2,%3}, [%4];"
        : "=r"(r[0]), "=r"(r[1]), "=r"(r[2]), "=r"(r[3]) : "r"(addr));
}
__device__ __forceinline__ void hmma(float* c, const uint32_t* a, uint32_t b0, uint32_t b1) {
    asm volatile("mma.sync.aligned.m16n8k16.row.col.f32.f16.f16.f32 "
        "{%0,%1,%2,%3},{%4,%5,%6,%7},{%8,%9},{%0,%1,%2,%3};"
        : "+f"(c[0]), "+f"(c[1]), "+f"(c[2]), "+f"(c[3])
        : "r"(a[0]), "r"(a[1]), "r"(a[2]), "r"(a[3]), "r"(b0), "r"(b1));
}
#define CPA_COMMIT() asm volatile("cp.async.commit_group;" ::: "memory")
__device__ __forceinline__ void cpa16(uint32_t dst, const void* src) {
    asm volatile("cp.async.cg.shared.global [%0], [%1], 16;" :: "r"(dst), "l"(src) : "memory");
}
__device__ __forceinline__ void cpa_tile8k(uint32_t dst, const unsigned char* src, int tid) {
#pragma unroll
    for (int rep = 0; rep < 4; rep++) {
        uint32_t o = (uint32_t)(rep * 128 + tid) * 16;
        cpa16(dst + o, src + o);
    }
}

// ---------------- fused prep ----------------
// blocks [0, 256)     : bmat (self-computed class tokens; 9 blocks also write
//                       g_tok v-part rows used by attn's epilogue)
// blocks [256, 12544) : qkv f32 -> swizzled fp16 tile images
__global__ void prep_kernel(const float* __restrict__ qkv, const int* __restrict__ mask,
                            const float* __restrict__ emb, const float* __restrict__ Wc)
{
    if (blockIdx.x >= 256) {
        int idx = (blockIdx.x - 256) * 256 + threadIdx.x;  // 64*192*256 total
        int t4 = (idx & 255) * 4;
        int ch = (idx >> 8) % 192;
        int bh = idx / (256 * 192);
        float4 v = *(const float4*)(qkv + (size_t)bh * 196608 + ch * 1024 + t4);
        uint32_t h0 = packh2(v.x, v.y), h1 = packh2(v.z, v.w);
        int tile = t4 >> 6, s = t4 & 63;
        uint32_t off = SW128((uint32_t)(ch & 63), (uint32_t)(s * 2));
        size_t base = ((size_t)bh * 16 + tile) * 8192;
        if (ch < 64)       *(uint2*)(g_q16 + base + off) = make_uint2(h0, h1);
        else if (ch < 128) *(uint2*)(g_k16 + base + off) = make_uint2(h0, h1);
        else               *(uint2*)(g_vh  + base + off) = make_uint2(h0, h1);
        return;
    }

    // ---- bmat block: compute tq locally, then bn2 + ratio table ----
    __shared__ float e[9 * 512];
    __shared__ float tq[576];
    const int fidx = blockIdx.x;                // 0..255
    const int bh = fidx & 63, sblk = fidx >> 6;
    const int b = bh >> 3;
    const int tid = threadIdx.x;
    const int w = tid >> 5, l = tid & 31;

    for (int x = tid; x < 4608; x += 256) e[x] = emb[x];
    __syncthreads();

    // tq[x] = dot(Wc[x&63], emb[x>>6]), 72 rows/warp, 4-way ILP shfl reduce
#pragma unroll
    for (int i0 = 0; i0 < 72; i0 += 4) {
        float acc[4];
#pragma unroll
        for (int j = 0; j < 4; j++) {
            int x = (i0 + j) * 8 + w;
            const float4* wr = (const float4*)(Wc + (x & 63) * 512);
            const float4* ee = (const float4*)(e + (x >> 6) * 512);
            float a = 0.f;
#pragma unroll
            for (int k = 0; k < 4; k++) {
                float4 p = wr[l + 32 * k], q = ee[l + 32 * k];
                a += p.x * q.x + p.y * q.y + p.z * q.z + p.w * q.w;
            }
            acc[j] = a;
        }
#pragma unroll
        for (int o = 16; o > 0; o >>= 1)
#pragma unroll
            for (int j = 0; j < 4; j++) acc[j] += __shfl_xor_sync(0xffffffffu, acc[j], o);
        if (l == 0)
#pragma unroll
            for (int j = 0; j < 4; j++) tq[(i0 + j) * 8 + w] = acc[j];
    }

    // 9 designated blocks also produce the token v-parts attn needs
    if (sblk == 0 && bh < 9) {
        const int c9 = bh;
        const float4* ee = (const float4*)(e + c9 * 512);
#pragma unroll
        for (int i = 0; i < 8; i++) {
            int cc = i * 8 + w;                 // 0..63
            const float4* wr = (const float4*)(Wc + (128 + cc) * 512);
            float a = 0.f;
#pragma unroll
            for (int k = 0; k < 4; k++) {
                float4 p = wr[l + 32 * k], q = ee[l + 32 * k];
                a += p.x * q.x + p.y * q.y + p.z * q.z + p.w * q.w;
            }
#pragma unroll
            for (int o = 16; o > 0; o >>= 1) a += __shfl_xor_sync(0xffffffffu, a, o);
            if (l == 0) g_tok[c9 * 192 + 128 + cc] = a;
        }
    }
    __syncthreads();

    const float* kb = qkv + bh * 196608 + 65536;
    int s = sblk * 256 + tid;
    float acc9[9];
#pragma unroll
    for (int c = 0; c < 9; c++) acc9[c] = 0.f;
#pragma unroll 4
    for (int c = 0; c < 64; c++) {
        float kv = kb[c * 1024 + s];
#pragma unroll
        for (int c9 = 0; c9 < 9; c9++) acc9[c9] = fmaf(tq[c9 * 64 + c], kv, acc9[c9]);
    }
    float bn = acc9[8];
    g_bn2[bh * 1024 + s] = SCL * bn;
    int sg = mask[b * 1024 + s];
#pragma unroll
    for (int c = 0; c < 8; c++)
        g_Rt[bh * 8192 + c * 1024 + s] =
            __float2half((sg == c) ? ex2f(SCL * (acc9[c] - bn)) : 0.f);
}

// ---------------- main kernel ----------------
// ring-3: slot i at i*16384 (K 8K + V 8K). Q staged in slot2's area (dead
// after prologue ldmatrix). OUT overlays slots 0/1 after the mainloop.
#define OFF_QTMP  32768u
#define OFF_R     49152u          /* Rt fp16 [8][1032] = 16512B */
#define OFF_BN2   65664u          /* 4096B */
#define OFF_TOKV  69760u          /* [9][68] f32 = 2448B */
#define OFF_SEGQ  72208u          /* 256B */
#define OFF_OUT   0u
#define SMEM_DYN  72576

__global__ void __launch_bounds__(128, 3)
attn_kernel(const float* __restrict__ qkv, const int* __restrict__ mask,
            float* __restrict__ out)
{
    extern __shared__ __align__(16) char smc[];
    const uint32_t sb = smem_u32(smc);

    const int tid = threadIdx.x;
    const int w = tid >> 5, lane = tid & 31;
    const int g = lane >> 2, tg = lane & 3;
    const int bh = blockIdx.y;
    const int qt = blockIdx.x;                 // 0..15 (64-row q tiles)
    const int t0 = qt * 64;
    const int b = bh >> 3;

    const unsigned char* q_g = g_q16 + ((size_t)bh * 16 + qt) * 8192;
    const unsigned char* k_g = g_k16 + ((size_t)bh * 16) * 8192;
    const unsigned char* v_g = g_vh + ((size_t)bh * 16) * 8192;

    // ---- prologue: G0 = Q(slot2 area) + Rt + bn2 ; G1 = chunk0 ; G2 = chunk1
    cpa_tile8k(sb + OFF_QTMP, q_g, tid);
    {
        const unsigned char* Rg = (const unsigned char*)(g_Rt + bh * 8192);
#pragma unroll
        for (int rep = 0; rep < 8; rep++) {
            int idx = rep * 128 + tid;              // 0..1023
            int row = idx >> 7, o16 = idx & 127;    // 128 x 16B = 2048B per row
            cpa16(sb + OFF_R + (uint32_t)row * 2064u + (uint32_t)o16 * 16u,
                  Rg + row * 2048 + o16 * 16);
        }
#pragma unroll
        for (int rep = 0; rep < 2; rep++) {
            uint32_t o = (uint32_t)(rep * 128 + tid) * 16;
            cpa16(sb + OFF_BN2 + o, (const unsigned char*)(g_bn2 + bh * 1024) + o);
        }
    }
    CPA_COMMIT();                                   // G0
    cpa_tile8k(sb + 0u,    k_g, tid);
    cpa_tile8k(sb + 8192u, v_g, tid);
    CPA_COMMIT();                                   // G1 = chunk 0 -> slot 0
    cpa_tile8k(sb + 16384u, k_g + 8192, tid);
    cpa_tile8k(sb + 24576u, v_g + 8192, tid);
    CPA_COMMIT();                                   // G2 = chunk 1 -> slot 1
    {
        float* tvs = (float*)(smc + OFF_TOKV);
        for (int x = tid; x < 576; x += 128)
            tvs[(x >> 6) * 68 + (x & 63)] = g_tok[(x >> 6) * 192 + 128 + (x & 63)];
        if (tid < 64) ((int*)(smc + OFF_SEGQ))[tid] = mask[b * 1024 + t0 + tid];
    }
    asm volatile("cp.async.wait_group 2;" ::: "memory");   // Q/Rt/bn2 ready
    __syncthreads();

    const int m0w = w * 16;
    const int ci_lo = ((const int*)(smc + OFF_SEGQ))[m0w + g];
    const int ci_hi = ((const int*)(smc + OFF_SEGQ))[m0w + g + 8];
    const uint32_t rb_lo = (uint32_t)ci_lo * 2064u;
    const uint32_t rb_hi = (uint32_t)ci_hi * 2064u;
    const char* Rtc = smc + OFF_R;
    const float* bn2sm = (const float*)(smc + OFF_BN2);

    // ---- persistent Q A-fragments, 4 k-steps (Q area is reused by slot 2
    //      starting at iteration 0's prefetch, which is after the first
    //      top-of-loop barrier -> all warps have read their frags by then) ----
    uint32_t qh[4][4];
    {
        int kkA = (lane & 7) + ((lane >> 4) << 3);
        int mmA = m0w + ((lane >> 3) & 1) * 8;
#pragma unroll
        for (int k = 0; k < 4; k++)
            ldsm4t(qh[k], sb + OFF_QTMP + SW128((uint32_t)(16 * k + kkA), (uint32_t)(mmA * 2)));
    }

    float accN[32], accC[32];
#pragma unroll
    for (int i = 0; i < 32; i++) { accN[i] = 0.f; accC[i] = 0.f; }
    float accSN[4] = {0.f, 0.f, 0.f, 0.f};
    float accSC[4] = {0.f, 0.f, 0.f, 0.f};
    const uint32_t bone = (lane < 4) ? 0x3C003C00u : 0u;

    const int kkB = lane & 15, nnB8 = (lane >> 4) * 8;
    const int nnV = (lane >> 4) * 8 + (lane & 7), kkV8 = ((lane >> 3) & 1) * 8;

    for (int chk = 0; chk < 16; chk++) {
        if (chk < 15) { asm volatile("cp.async.wait_group 1;" ::: "memory"); }
        else          { asm volatile("cp.async.wait_group 0;" ::: "memory"); }
        __syncthreads();   // chunk chk visible; slot (chk+2)%3 free (last read chunk chk-1)

        if (chk + 2 < 16) {
            const uint32_t nb = (uint32_t)((chk + 2) % 3) * 16384u;
            cpa_tile8k(sb + nb + 0u,    k_g + (chk + 2) * 8192, tid);
            cpa_tile8k(sb + nb + 8192u, v_g + (chk + 2) * 8192, tid);
            CPA_COMMIT();
        }

        const uint32_t bufb = (uint32_t)(chk % 3) * 16384u;
        const uint32_t bKH = sb + bufb, bV = sb + bufb + 8192u;
        const int s0 = chk * 64;

#pragma unroll
        for (int ntp = 0; ntp < 4; ntp++) {
            float S[8];
#pragma unroll
            for (int i = 0; i < 8; i++) S[i] = 0.f;
#pragma unroll
            for (int k = 0; k < 4; k++) {
                uint32_t bh4[4];
                ldsm4t(bh4, bKH + SW128((uint32_t)(16 * k + kkB), (uint32_t)((ntp * 16 + nnB8) * 2)));
                hmma(S, qh[k], bh4[0], bh4[1]);
                hmma(S + 4, qh[k], bh4[2], bh4[3]);
            }
            uint32_t aN[4], aC[4];
#pragma unroll
            for (int t = 0; t < 2; t++) {
                const int sA = s0 + ntp * 16 + t * 8 + 2 * tg;
                float2 b2 = *(const float2*)(bn2sm + sA);
                float x0 = fmaf(S[4 * t + 0], SCL, b2.x);
                float x1 = fmaf(S[4 * t + 1], SCL, b2.y);
                float x2 = fmaf(S[4 * t + 2], SCL, b2.x);
                float x3 = fmaf(S[4 * t + 3], SCL, b2.y);
                aN[2 * t]     = ex2h2(packh2(x0, x1));
                aN[2 * t + 1] = ex2h2(packh2(x2, x3));
                uint32_t rl = *(const uint32_t*)(Rtc + rb_lo + sA * 2);
                uint32_t rh = *(const uint32_t*)(Rtc + rb_hi + sA * 2);
                aC[2 * t]     = mulh2(aN[2 * t], rl);
                aC[2 * t + 1] = mulh2(aN[2 * t + 1], rh);
            }
            hmma(accSN, aN, bone, bone);
            hmma(accSC, aC, bone, bone);
            const int k0v = ntp * 16;
#pragma unroll
            for (int np = 0; np < 4; np++) {
                uint32_t bv[4];
                ldsm4(bv, bV + SW128((uint32_t)(np * 16 + nnV), (uint32_t)((k0v + kkV8) * 2)));
                hmma(accN + (2 * np) * 4, aN, bv[0], bv[1]);
                hmma(accC + (2 * np) * 4, aC, bv[0], bv[1]);
                hmma(accN + (2 * np + 1) * 4, aN, bv[2], bv[3]);
                hmma(accC + (2 * np + 1) * 4, aC, bv[2], bv[3]);
            }
        }
    }
    __syncthreads();       // everyone done reading ring before OUT overlay

    // ---- extract row sums: col 0 lives in the tg==0 lane of each group ----
    const int src = lane & ~3;
    const float sNlo = __shfl_sync(0xffffffffu, accSN[0], src);
    const float sNhi = __shfl_sync(0xffffffffu, accSN[2], src);
    const float sClo = __shfl_sync(0xffffffffu, accSC[0], src);
    const float sChi = __shfl_sync(0xffffffffu, accSC[2], src);
    const float rsNlo = 0.5f / sNlo, rsNhi = 0.5f / sNhi;
    const float rsClo = 0.5f / sClo, rsChi = 0.5f / sChi;

    // ---- stage normalized output to smem [64c][64q] pitch 68 f32 ----
    {
        float* so = (float*)(smc + OFF_OUT);
        const float* tv8 = (const float*)(smc + OFF_TOKV) + 8 * 68;
        const float* tvl = (const float*)(smc + OFF_TOKV) + ci_lo * 68;
        const float* tvh = (const float*)(smc + OFF_TOKV) + ci_hi * 68;
#pragma unroll
        for (int nt = 0; nt < 8; nt++) {
            int c0 = nt * 8 + 2 * tg;
            so[c0 * 68 + m0w + g] =
                accN[nt * 4 + 0] * rsNlo + accC[nt * 4 + 0] * rsClo + 0.5f * (tv8[c0] + tvl[c0]);
            so[(c0 + 1) * 68 + m0w + g] =
                accN[nt * 4 + 1] * rsNlo + accC[nt * 4 + 1] * rsClo + 0.5f * (tv8[c0 + 1] + tvl[c0 + 1]);
            so[c0 * 68 + m0w + g + 8] =
                accN[nt * 4 + 2] * rsNhi + accC[nt * 4 + 2] * rsChi + 0.5f * (tv8[c0] + tvh[c0]);
            so[(c0 + 1) * 68 + m0w + g + 8] =
                accN[nt * 4 + 3] * rsNhi + accC[nt * 4 + 3] * rsChi + 0.5f * (tv8[c0 + 1] + tvh[c0 + 1]);
        }
    }
    __syncthreads();

    // ---- coalesced copy-out: out[c*65536 + bh*1024 + t0 + t] ----
    {
        const float* so = (const float*)(smc + OFF_OUT);
#pragma unroll
        for (int rep = 0; rep < 8; rep++) {
            int idx = rep * 128 + tid;
            int c = idx >> 4, q4 = (idx & 15) * 4;
            float4 v = *(const float4*)(so + c * 68 + q4);
            *(float4*)(out + c * 65536 + bh * 1024 + t0 + q4) = v;
        }
    }
}

// ---------------------------------------------------------------------------
extern "C" void kernel_launch(void* const* d_in, const int* in_sizes, int n_in,
                              void* d_out, int out_size)
{
    const float* qkv  = (const float*)d_in[0];
    const int*   mask = (const int*)  d_in[1];
    const float* emb  = (const float*)d_in[2];
    const float* Wc   = (const float*)d_in[3];
    float* out = (float*)d_out;

    prep_kernel<<<12544, 256>>>(qkv, mask, emb, Wc);
    cudaFuncSetAttribute(attn_kernel, cudaFuncAttributeMaxDynamicSharedMemorySize, SMEM_DYN);
    attn_kernel<<<dim3(16, 64), 128, SMEM_DYN>>>(qkv, mask, out);
}

// round 14
// speedup vs baseline: 2.5660x; 2.5660x over previous
#include <cuda_runtime.h>
#include <cuda_fp16.h>
#include <cstdint>

// ============================================================================
// out[t] = 0.5*( softmaxN(G+Bn)V + vn + softmaxC(G+Bc; seg==c_t)V + vc )
// G = Q.K^T via mma.sync HMMA fp16. Unnormalized exp2 weights as PV A-frags;
// two fp32 accumulators; counter==2.
// R14: REVERT to R12 (proven 98.1us) + bmat blocks first in prep grid +
// wider tok_kernel (1 row/warp). attn numerics identical to R12.
// ============================================================================

#define SCL 0.18033688011112042f   // 0.125 * log2(e)

__device__ float g_tok[9 * 192];
__device__ __half g_Rt[64 * 8 * 1024];  // [bh][c][s] masked exp2(SCL*(Bc-Bn)), fp16
__device__ float g_bn2[64 * 1024];      // [bh][s] = SCL*Bn
// preconverted fp16 tile images (swizzled smem byte-images, pitch-128 tiles)
__device__ __align__(16) unsigned char g_q16[64 * 16 * 8192];   // [bh][qtile 64t]
__device__ __align__(16) unsigned char g_k16[64 * 16 * 8192];   // [bh][ktile 64s]
__device__ __align__(16) unsigned char g_vh [64 * 16 * 8192];   // [bh][vtile 64s]

__device__ __forceinline__ uint32_t smem_u32(const void* p) {
    uint32_t a;
    asm("{ .reg .u64 t; cvta.to.shared.u64 t, %1; cvt.u32.u64 %0, t; }" : "=r"(a) : "l"(p));
    return a;
}
__device__ __forceinline__ float ex2f(float x) {
    float y; asm("ex2.approx.f32 %0, %1;" : "=f"(y) : "f"(x)); return y;
}
__device__ __forceinline__ uint32_t ex2h2(uint32_t x) {
    uint32_t r; asm("ex2.approx.f16x2 %0, %1;" : "=r"(r) : "r"(x)); return r;
}
__device__ __forceinline__ uint32_t packh2(float lo, float hi) {
    uint32_t r; asm("cvt.rn.f16x2.f32 %0, %1, %2;" : "=r"(r) : "f"(hi), "f"(lo)); return r;
}
__device__ __forceinline__ uint32_t mulh2(uint32_t a, uint32_t b) {
    uint32_t r; asm("mul.rn.f16x2 %0, %1, %2;" : "=r"(r) : "r"(a), "r"(b)); return r;
}
// pitch-128 swizzle for 64-wide fp16 tiles: row=ch, byte col = s*2
__device__ __forceinline__ uint32_t SW128(uint32_t row, uint32_t bcol) {
    return row * 128u + (bcol ^ ((row & 7u) << 4));
}
__device__ __forceinline__ void ldsm4t(uint32_t* r, uint32_t addr) {
    asm volatile("ldmatrix.sync.aligned.m8n8.x4.trans.shared.b16 {%0,%1,%2,%3}, [%4];"
        : "=r"(r[0]), "=r"(r[1]), "=r"(r[2]), "=r"(r[3]) : "r"(addr));
}
__device__ __forceinline__ void ldsm4(uint32_t* r, uint32_t addr) {
    asm volatile("ldmatrix.sync.aligned.m8n8.x4.shared.b16 {%0,%1,%2,%3}, [%4];"
        : "=r"(r[0]), "=r"(r[1]), "=r"(r[2]), "=r"(r[3]) : "r"(addr));
}
__device__ __forceinline__ void hmma(float* c, const uint32_t* a, uint32_t b0, uint32_t b1) {
    asm volatile("mma.sync.aligned.m16n8k16.row.col.f32.f16.f16.f32 "
        "{%0,%1,%2,%3},{%4,%5,%6,%7},{%8,%9},{%0,%1,%2,%3};"
        : "+f"(c[0]), "+f"(c[1]), "+f"(c[2]), "+f"(c[3])
        : "r"(a[0]), "r"(a[1]), "r"(a[2]), "r"(a[3]), "r"(b0), "r"(b1));
}
#define CPA_COMMIT() asm volatile("cp.async.commit_group;" ::: "memory")
__device__ __forceinline__ void cpa16(uint32_t dst, const void* src) {
    asm volatile("cp.async.cg.shared.global [%0], [%1], 16;" :: "r"(dst), "l"(src) : "memory");
}
__device__ __forceinline__ void cpa_tile8k(uint32_t dst, const unsigned char* src, int tid) {
#pragma unroll
    for (int rep = 0; rep < 4; rep++) {
        uint32_t o = (uint32_t)(rep * 128 + tid) * 16;
        cpa16(dst + o, src + o);
    }
}

// ---------------- aux A: class tokens (grid 9 x 24, 1 row/warp) ----------------
__global__ void tok_kernel(const float* __restrict__ emb, const float* __restrict__ Wc)
{
    __shared__ float e[512];
    int c9 = blockIdx.x;
    for (int k = threadIdx.x; k < 512; k += 256) e[k] = emb[c9 * 512 + k];
    __syncthreads();
    int w = threadIdx.x >> 5, l = threadIdx.x & 31;
    int r = blockIdx.y * 8 + w;               // 0..191
    const float* wr = Wc + r * 512;
    float acc = 0.f;
#pragma unroll
    for (int k = 0; k < 16; k++) acc = fmaf(wr[l + 32 * k], e[l + 32 * k], acc);
#pragma unroll
    for (int o = 16; o > 0; o >>= 1) acc += __shfl_xor_sync(0xffffffffu, acc, o);
    if (l == 0) g_tok[c9 * 192 + r] = acc;
}

// ---------------- fused prep: bn2/ratio table (first) + preconvert tiles ----------------
// blocks [0, 256)     : bmat (reads g_tok from tok_kernel)
// blocks [256, 12544) : qkv f32 -> swizzled fp16 tile images
__global__ void prep_kernel(const float* __restrict__ qkv, const int* __restrict__ mask)
{
    if (blockIdx.x >= 256) {
        int idx = (blockIdx.x - 256) * 256 + threadIdx.x;  // 64*192*256 total
        int t4 = (idx & 255) * 4;
        int ch = (idx >> 8) % 192;
        int bh = idx / (256 * 192);
        float4 v = *(const float4*)(qkv + (size_t)bh * 196608 + ch * 1024 + t4);
        uint32_t h0 = packh2(v.x, v.y), h1 = packh2(v.z, v.w);
        int tile = t4 >> 6, s = t4 & 63;
        uint32_t off = SW128((uint32_t)(ch & 63), (uint32_t)(s * 2));
        size_t base = ((size_t)bh * 16 + tile) * 8192;
        if (ch < 64)       *(uint2*)(g_q16 + base + off) = make_uint2(h0, h1);
        else if (ch < 128) *(uint2*)(g_k16 + base + off) = make_uint2(h0, h1);
        else               *(uint2*)(g_vh  + base + off) = make_uint2(h0, h1);
    } else {
        __shared__ float tq[9 * 64];
        int fidx = blockIdx.x;                             // 0..255
        int bh = fidx & 63, sblk = fidx >> 6;
        int b = bh >> 3;
        for (int x = threadIdx.x; x < 576; x += 256) tq[x] = g_tok[(x >> 6) * 192 + (x & 63)];
        __syncthreads();
        const float* kb = qkv + bh * 196608 + 65536;
        int s = sblk * 256 + threadIdx.x;
        float acc[9];
#pragma unroll
        for (int c = 0; c < 9; c++) acc[c] = 0.f;
#pragma unroll 4
        for (int c = 0; c < 64; c++) {
            float kv = kb[c * 1024 + s];
#pragma unroll
            for (int c9 = 0; c9 < 9; c9++) acc[c9] = fmaf(tq[c9 * 64 + c], kv, acc[c9]);
        }
        float bn = acc[8];
        g_bn2[bh * 1024 + s] = SCL * bn;
        int sg = mask[b * 1024 + s];
#pragma unroll
        for (int c = 0; c < 8; c++)
            g_Rt[bh * 8192 + c * 1024 + s] =
                __float2half((sg == c) ? ex2f(SCL * (acc[c] - bn)) : 0.f);
    }
}

// ---------------- main kernel (EXACT R12) ----------------
#define OFF_QH    0u
#define OFF_BUF   8192u           /* ring-2: (K 8K + V 8K) x2 = 32KB */
#define OFF_R     40960u          /* Rt fp16 [8][1032] = 16512B */
#define OFF_BN2   57472u          /* 4096B */
#define OFF_TOKV  61568u          /* [9][68] f32 = 2448B */
#define OFF_SEGQ  64016u          /* 256B */
#define OFF_OUT   8192u           /* overlay on ring buffers after mainloop */
#define SMEM_DYN  64384

__global__ void __launch_bounds__(128, 3)
attn_kernel(const float* __restrict__ qkv, const int* __restrict__ mask,
            float* __restrict__ out)
{
    extern __shared__ __align__(16) char smc[];
    const uint32_t sb = smem_u32(smc);

    const int tid = threadIdx.x;
    const int w = tid >> 5, lane = tid & 31;
    const int g = lane >> 2, tg = lane & 3;
    const int bh = blockIdx.y;
    const int qt = blockIdx.x;                 // 0..15 (64-row q tiles)
    const int t0 = qt * 64;
    const int b = bh >> 3;

    const unsigned char* q_g = g_q16 + ((size_t)bh * 16 + qt) * 8192;
    const unsigned char* k_g = g_k16 + ((size_t)bh * 16) * 8192;
    const unsigned char* v_g = g_vh + ((size_t)bh * 16) * 8192;

    // ---- prologue: G0 = Q + Rt + bn2 ; G1 = chunk0 ; G2 = chunk1 ----
    cpa_tile8k(sb + OFF_QH, q_g, tid);
    {
        const unsigned char* Rg = (const unsigned char*)(g_Rt + bh * 8192);
#pragma unroll
        for (int rep = 0; rep < 8; rep++) {
            int idx = rep * 128 + tid;              // 0..1023
            int row = idx >> 7, o16 = idx & 127;    // 128 x 16B = 2048B per row
            cpa16(sb + OFF_R + (uint32_t)row * 2064u + (uint32_t)o16 * 16u,
                  Rg + row * 2048 + o16 * 16);
        }
#pragma unroll
        for (int rep = 0; rep < 2; rep++) {
            uint32_t o = (uint32_t)(rep * 128 + tid) * 16;
            cpa16(sb + OFF_BN2 + o, (const unsigned char*)(g_bn2 + bh * 1024) + o);
        }
    }
    CPA_COMMIT();
    cpa_tile8k(sb + OFF_BUF + 0u,    k_g, tid);
    cpa_tile8k(sb + OFF_BUF + 8192u, v_g, tid);
    CPA_COMMIT();
    cpa_tile8k(sb + OFF_BUF + 16384u, k_g + 8192, tid);
    cpa_tile8k(sb + OFF_BUF + 24576u, v_g + 8192, tid);
    CPA_COMMIT();
    {
        float* tvs = (float*)(smc + OFF_TOKV);
        for (int x = tid; x < 576; x += 128)
            tvs[(x >> 6) * 68 + (x & 63)] = g_tok[(x >> 6) * 192 + 128 + (x & 63)];
        if (tid < 64) ((int*)(smc + OFF_SEGQ))[tid] = mask[b * 1024 + t0 + tid];
    }
    asm volatile("cp.async.wait_group 2;" ::: "memory");   // Q/Rt/bn2 ready
    __syncthreads();

    const int m0w = w * 16;
    const int ci_lo = ((const int*)(smc + OFF_SEGQ))[m0w + g];
    const int ci_hi = ((const int*)(smc + OFF_SEGQ))[m0w + g + 8];
    const uint32_t rb_lo = (uint32_t)ci_lo * 2064u;
    const uint32_t rb_hi = (uint32_t)ci_hi * 2064u;
    const char* Rtc = smc + OFF_R;
    const float* bn2sm = (const float*)(smc + OFF_BN2);

    // ---- persistent Q A-fragments, 4 k-steps ----
    uint32_t qh[4][4];
    {
        int kkA = (lane & 7) + ((lane >> 4) << 3);
        int mmA = m0w + ((lane >> 3) & 1) * 8;
#pragma unroll
        for (int k = 0; k < 4; k++)
            ldsm4t(qh[k], sb + OFF_QH + SW128((uint32_t)(16 * k + kkA), (uint32_t)(mmA * 2)));
    }

    float accN[32], accC[32];
#pragma unroll
    for (int i = 0; i < 32; i++) { accN[i] = 0.f; accC[i] = 0.f; }
    // row-sum accumulators via ones-column HMMA (col 0 = sum)
    float accSN[4] = {0.f, 0.f, 0.f, 0.f};
    float accSC[4] = {0.f, 0.f, 0.f, 0.f};
    // constant B fragment: B[k][n]=1 iff n==0 -> lanes 0..3 (gid 0) hold ones
    const uint32_t bone = (lane < 4) ? 0x3C003C00u : 0u;

    const int kkB = lane & 15, nnB8 = (lane >> 4) * 8;
    const int nnV = (lane >> 4) * 8 + (lane & 7), kkV8 = ((lane >> 3) & 1) * 8;

    for (int chk = 0; chk < 16; chk++) {
        if (chk < 15) { asm volatile("cp.async.wait_group 1;" ::: "memory"); }
        else          { asm volatile("cp.async.wait_group 0;" ::: "memory"); }
        __syncthreads();                       // chunk chk visible to all

        const uint32_t bufb = OFF_BUF + (uint32_t)(chk & 1) * 16384u;
        const uint32_t bKH = sb + bufb, bV = sb + bufb + 8192u;
        const int s0 = chk * 64;

#pragma unroll
        for (int ntp = 0; ntp < 4; ntp++) {
            float S[8];
#pragma unroll
            for (int i = 0; i < 8; i++) S[i] = 0.f;
#pragma unroll
            for (int k = 0; k < 4; k++) {
                uint32_t bh4[4];
                ldsm4t(bh4, bKH + SW128((uint32_t)(16 * k + kkB), (uint32_t)((ntp * 16 + nnB8) * 2)));
                hmma(S, qh[k], bh4[0], bh4[1]);
                hmma(S + 4, qh[k], bh4[2], bh4[3]);
            }
            uint32_t aN[4], aC[4];
#pragma unroll
            for (int t = 0; t < 2; t++) {
                const int sA = s0 + ntp * 16 + t * 8 + 2 * tg;
                float2 b2 = *(const float2*)(bn2sm + sA);
                float x0 = fmaf(S[4 * t + 0], SCL, b2.x);
                float x1 = fmaf(S[4 * t + 1], SCL, b2.y);
                float x2 = fmaf(S[4 * t + 2], SCL, b2.x);
                float x3 = fmaf(S[4 * t + 3], SCL, b2.y);
                aN[2 * t]     = ex2h2(packh2(x0, x1));   // exp2 on half2 args
                aN[2 * t + 1] = ex2h2(packh2(x2, x3));
                uint32_t rl = *(const uint32_t*)(Rtc + rb_lo + sA * 2);
                uint32_t rh = *(const uint32_t*)(Rtc + rb_hi + sA * 2);
                aC[2 * t]     = mulh2(aN[2 * t], rl);
                aC[2 * t + 1] = mulh2(aN[2 * t + 1], rh);
            }
            // row sums via ones-column (tensor pipe)
            hmma(accSN, aN, bone, bone);
            hmma(accSC, aC, bone, bone);
            // PV for this 16-s group
            const int k0v = ntp * 16;
#pragma unroll
            for (int np = 0; np < 4; np++) {
                uint32_t bv[4];
                ldsm4(bv, bV + SW128((uint32_t)(np * 16 + nnV), (uint32_t)((k0v + kkV8) * 2)));
                hmma(accN + (2 * np) * 4, aN, bv[0], bv[1]);
                hmma(accC + (2 * np) * 4, aC, bv[0], bv[1]);
                hmma(accN + (2 * np + 1) * 4, aN, bv[2], bv[3]);
                hmma(accC + (2 * np + 1) * 4, aC, bv[2], bv[3]);
            }
        }
        __syncthreads();                       // slot chk&1 fully consumed
        if (chk + 2 < 16) {
            const uint32_t nb = OFF_BUF + (uint32_t)(chk & 1) * 16384u;
            cpa_tile8k(sb + nb + 0u,    k_g + (chk + 2) * 8192, tid);
            cpa_tile8k(sb + nb + 8192u, v_g + (chk + 2) * 8192, tid);
            CPA_COMMIT();
        }
    }

    // ---- extract row sums: col 0 lives in the tg==0 lane of each group ----
    const int src = lane & ~3;
    const float sNlo = __shfl_sync(0xffffffffu, accSN[0], src);
    const float sNhi = __shfl_sync(0xffffffffu, accSN[2], src);
    const float sClo = __shfl_sync(0xffffffffu, accSC[0], src);
    const float sChi = __shfl_sync(0xffffffffu, accSC[2], src);
    const float rsNlo = 0.5f / sNlo, rsNhi = 0.5f / sNhi;
    const float rsClo = 0.5f / sClo, rsChi = 0.5f / sChi;

    // ---- stage normalized output to smem [64c][64q] pitch 68 f32 ----
    {
        float* so = (float*)(smc + OFF_OUT);
        const float* tv8 = (const float*)(smc + OFF_TOKV) + 8 * 68;
        const float* tvl = (const float*)(smc + OFF_TOKV) + ci_lo * 68;
        const float* tvh = (const float*)(smc + OFF_TOKV) + ci_hi * 68;
#pragma unroll
        for (int nt = 0; nt < 8; nt++) {
            int c0 = nt * 8 + 2 * tg;
            so[c0 * 68 + m0w + g] =
                accN[nt * 4 + 0] * rsNlo + accC[nt * 4 + 0] * rsClo + 0.5f * (tv8[c0] + tvl[c0]);
            so[(c0 + 1) * 68 + m0w + g] =
                accN[nt * 4 + 1] * rsNlo + accC[nt * 4 + 1] * rsClo + 0.5f * (tv8[c0 + 1] + tvl[c0 + 1]);
            so[c0 * 68 + m0w + g + 8] =
                accN[nt * 4 + 2] * rsNhi + accC[nt * 4 + 2] * rsChi + 0.5f * (tv8[c0] + tvh[c0]);
            so[(c0 + 1) * 68 + m0w + g + 8] =
                accN[nt * 4 + 3] * rsNhi + accC[nt * 4 + 3] * rsChi + 0.5f * (tv8[c0 + 1] + tvh[c0 + 1]);
        }
    }
    __syncthreads();

    // ---- coalesced copy-out: out[c*65536 + bh*1024 + t0 + t] ----
    {
        const float* so = (const float*)(smc + OFF_OUT);
#pragma unroll
        for (int rep = 0; rep < 8; rep++) {
            int idx = rep * 128 + tid;
            int c = idx >> 4, q4 = (idx & 15) * 4;
            float4 v = *(const float4*)(so + c * 68 + q4);
            *(float4*)(out + c * 65536 + bh * 1024 + t0 + q4) = v;
        }
    }
}

// ---------------------------------------------------------------------------
extern "C" void kernel_launch(void* const* d_in, const int* in_sizes, int n_in,
                              void* d_out, int out_size)
{
    const float* qkv  = (const float*)d_in[0];
    const int*   mask = (const int*)  d_in[1];
    const float* emb  = (const float*)d_in[2];
    const float* Wc   = (const float*)d_in[3];
    float* out = (float*)d_out;

    tok_kernel<<<dim3(9, 24), 256>>>(emb, Wc);
    prep_kernel<<<12544, 256>>>(qkv, mask);
    cudaFuncSetAttribute(attn_kernel, cudaFuncAttributeMaxDynamicSharedMemorySize, SMEM_DYN);
    attn_kernel<<<dim3(16, 64), 128, SMEM_DYN>>>(qkv, mask, out);
}